// round 10
// baseline (speedup 1.0000x reference)
#include <cuda_runtime.h>
#include <cstdint>

#define H 256
#define DD 64
#define NB 128              // blocks; 2 output neurons each; single wave guaranteed

// ---------------- persistent device state (no allocations) ----------------
__device__ float g_G[H * H];                      // Gram: G[m,t]
__device__ float g_h1[H], g_h2[H], g_h3[H], g_h4[H], g_s[H], g_h[H];
__device__ unsigned int g_bar = 0;
__device__ double g_accum = 0.0;
__device__ unsigned int g_done = 0;

// ---------------- single fused kernel ----------------
// Phase A: block b -> Gram rows 2b,2b+1 (warps 0-7). Block 0 warps 8-15 also
//          compute the layer-1 tanh chain (h1..h4, s, h) and publish to gmem.
// Device-wide barrier (all NB blocks resident: 1 block/SM, NB <= SM count).
// Phase B: per-block (n0,n0+1) coefficients from 6 L2-hot loads; stream G
//          (float4, 8-deep batches) accumulating M/P; contraction; one atomic.
__global__ __launch_bounds__(512) void k_all(
    const float* __restrict__ x,  const float* __restrict__ W1,
    const float* __restrict__ b1, const float* __restrict__ W2,
    const float* __restrict__ b2, const float* __restrict__ W3,
    float* __restrict__ out)
{
    __shared__ float  sP[8 * 64 * 16];   // partials [ms][ts][16] = 32KB
    __shared__ float4 sAB[H];            // {A0, A1, B0, B1} per m (4KB)
    __shared__ float  sU0[H], sU1[H], sh[H];
    __shared__ float  sx[DD];
    __shared__ float  srow[2][DD];
    __shared__ float  sgd[8];
    __shared__ float  sred[8 * 12];

    int tid = threadIdx.x;
    int b = blockIdx.x;
    int wid = tid >> 5, lane = tid & 31;
    int n0 = 2 * b;

    if (tid < DD) sx[tid] = x[tid];
    if (tid >= 64 && tid < 192) {
        int r = (tid - 64) >> 6, c = (tid - 64) & 63;
        srow[r][c] = W1[(2 * b + r) * DD + c];
    }
    __syncthreads();

    // ---- phase A ----
    if (b == 0 && tid >= 256) {
        // layer-1 forward + tanh derivative chains (once, block 0 warps 8-15)
        int m = tid - 256;
        float z = b1[m], s = 0.f;
        const float4* wr = (const float4*)(W1 + m * DD);
#pragma unroll
        for (int i = 0; i < DD / 4; i++) {
            float4 w = __ldg(wr + i);
            float4 xv = *(const float4*)(sx + 4 * i);
            z += w.x * xv.x + w.y * xv.y + w.z * xv.z + w.w * xv.w;
            s += w.x * w.x + w.y * w.y + w.z * w.z + w.w * w.w;
        }
        float h = tanhf(z), w = 1.f - h * h;
        g_h1[m] = w;
        g_h2[m] = -2.f * h * w;
        g_h3[m] = (4.f * h * h - 2.f * w) * w;
        g_h4[m] = (16.f * w - 8.f * h * h) * h * w;
        g_s[m] = s;
        g_h[m] = h;
    } else if (tid < 256) {
        // Gram rows 2b, 2b+1
        int t = tid;
        const float4* myr = (const float4*)(W1 + t * DD);
        float a0 = 0.f, a1 = 0.f;
#pragma unroll
        for (int i = 0; i < DD / 4; i++) {
            float4 v = __ldg(myr + i);
            a0 += srow[0][4*i]*v.x + srow[0][4*i+1]*v.y + srow[0][4*i+2]*v.z + srow[0][4*i+3]*v.w;
            a1 += srow[1][4*i]*v.x + srow[1][4*i+1]*v.y + srow[1][4*i+2]*v.z + srow[1][4*i+3]*v.w;
        }
        g_G[(2 * b + 0) * H + t] = a0;
        g_G[(2 * b + 1) * H + t] = a1;
    }

    // ---- device-wide barrier (all NB blocks resident in one wave) ----
    __syncthreads();
    if (tid == 0) {
        __threadfence();
        unsigned int arr = atomicAdd(&g_bar, 1u) + 1u;
        while (arr < NB) {
            __nanosleep(64);
            arr = atomicAdd(&g_bar, 0u);
        }
        __threadfence();
    }
    __syncthreads();

    // ---- phase B setup: coefficients from published chain vectors ----
    float pL0 = 0.f, pL1 = 0.f, pY0 = 0.f, pY1 = 0.f;
    if (tid < H) {
        int m = tid;
        float h1 = g_h1[m], h2 = g_h2[m], h3 = g_h3[m], h4 = g_h4[m], s = g_s[m];
        float w20 = __ldg(&W2[n0 * H + m]);
        float w21 = __ldg(&W2[(n0 + 1) * H + m]);
        float A0 = w20 * h1, A1 = w21 * h1;
        float B0 = w20 * h2, B1 = w21 * h2;
        sAB[m] = make_float4(A0, A1, B0, B1);
        sU0[m] = w20 * h3 * s;
        sU1[m] = w21 * h3 * s;
        pL0 = B0 * s;  pL1 = B1 * s;
        pY0 = w20 * h4 * s * s;
        pY1 = w21 * h4 * s * s;
        sh[m] = g_h[m];
    }
    __syncthreads();

    // warps 0,1: a_n = W2[n].h + b2[n] -> g'..g'''' into sgd
    if (wid < 2) {
        int n = n0 + wid;
        float a = 0.f;
#pragma unroll
        for (int k = 0; k < 8; k++) {
            int m = lane + 32 * k;
            a += __ldg(&W2[n * H + m]) * sh[m];
        }
#pragma unroll
        for (int s = 16; s > 0; s >>= 1) a += __shfl_down_sync(0xFFFFFFFFu, a, s);
        if (lane == 0) {
            a += b2[n];
            float g = tanhf(a), gw = 1.f - g * g;
            sgd[wid * 4 + 0] = gw;
            sgd[wid * 4 + 1] = -2.f * g * gw;
            sgd[wid * 4 + 2] = (4.f * g * g - 2.f * gw) * gw;
            sgd[wid * 4 + 3] = (16.f * gw - 8.f * g * g) * g * gw;
        }
    }

    // ---- phase 1: stream G from global, 4 t-cols x 32 m per thread ----
    int ms = tid >> 6, ts = tid & 63;
    float M0[4] = {0,0,0,0}, M1[4] = {0,0,0,0};
    float P0[4] = {0,0,0,0}, P1[4] = {0,0,0,0};

    const float4* Gp = (const float4*)g_G + (32 * ms) * (H / 4) + ts;
    const float4* abp = sAB + 32 * ms;

#pragma unroll
    for (int bb = 0; bb < 4; bb++) {
        float4 gv[8];
#pragma unroll
        for (int u = 0; u < 8; u++) gv[u] = __ldg(Gp + (8 * bb + u) * (H / 4));
#pragma unroll
        for (int u = 0; u < 8; u++) {
            float4 ab = abp[8 * bb + u];
            float4 g = gv[u];
            M0[0] += ab.x * g.x;  M0[1] += ab.x * g.y;  M0[2] += ab.x * g.z;  M0[3] += ab.x * g.w;
            M1[0] += ab.y * g.x;  M1[1] += ab.y * g.y;  M1[2] += ab.y * g.z;  M1[3] += ab.y * g.w;
            float gg0 = g.x * g.x, gg1 = g.y * g.y, gg2 = g.z * g.z, gg3 = g.w * g.w;
            P0[0] += ab.z * gg0;  P0[1] += ab.z * gg1;  P0[2] += ab.z * gg2;  P0[3] += ab.z * gg3;
            P1[0] += ab.w * gg0;  P1[1] += ab.w * gg1;  P1[2] += ab.w * gg2;  P1[3] += ab.w * gg3;
        }
    }

    {
        float4* sp = (float4*)(sP + (ms * 64 + ts) * 16);
        sp[0] = make_float4(M0[0], M0[1], M0[2], M0[3]);
        sp[1] = make_float4(M1[0], M1[1], M1[2], M1[3]);
        sp[2] = make_float4(P0[0], P0[1], P0[2], P0[3]);
        sp[3] = make_float4(P1[0], P1[1], P1[2], P1[3]);
    }
    __syncthreads();

    // ---- phase 2: combine partials + contraction (threads 0-255, t = tid) ----
    if (tid < H) {
        int tts = tid >> 2, c = tid & 3;
        float m0 = 0.f, m1 = 0.f, q0 = 0.f, q1 = 0.f;
#pragma unroll
        for (int w = 0; w < 8; w++) {
            const float* sp = sP + (w * 64 + tts) * 16;
            m0 += sp[c];
            m1 += sp[4 + c];
            q0 += sp[8 + c];
            q1 += sp[12 + c];
        }

        float4 ab = sAB[tid];
        float p[12];
        p[0]  = ab.x * m0;        p[1]  = ab.z * m0 * m0;  p[2]  = ab.z * q0;
        p[3]  = sU0[tid] * m0;    p[4]  = pL0;             p[5]  = pY0;
        p[6]  = ab.y * m1;        p[7]  = ab.w * m1 * m1;  p[8]  = ab.w * q1;
        p[9]  = sU1[tid] * m1;    p[10] = pL1;             p[11] = pY1;

#pragma unroll
        for (int k = 0; k < 12; k++) {
            float v = p[k];
#pragma unroll
            for (int s = 16; s > 0; s >>= 1) v += __shfl_down_sync(0xFFFFFFFFu, v, s);
            p[k] = v;
        }
        if (lane == 0) {
#pragma unroll
            for (int k = 0; k < 12; k++) sred[wid * 12 + k] = p[k];
        }
    }
    __syncthreads();

    if (tid == 0) {
        double dsum = 0.0;
#pragma unroll
        for (int nn = 0; nn < 2; nn++) {
            float Q = 0.f, R = 0.f, Z = 0.f, U = 0.f, L = 0.f, Y = 0.f;
#pragma unroll
            for (int w = 0; w < 8; w++) {
                Q += sred[w * 12 + nn * 6 + 0];
                R += sred[w * 12 + nn * 6 + 1];
                Z += sred[w * 12 + nn * 6 + 2];
                U += sred[w * 12 + nn * 6 + 3];
                L += sred[w * 12 + nn * 6 + 4];
                Y += sred[w * 12 + nn * 6 + 5];
            }
            float g1 = sgd[nn * 4 + 0], g2 = sgd[nn * 4 + 1];
            float g3 = sgd[nn * 4 + 2], g4 = sgd[nn * 4 + 3];
            float val = g4 * Q * Q
                      + g3 * (2.f * L * Q + 4.f * R)
                      + g2 * (L * L + 2.f * Z + 4.f * U)
                      + g1 * Y;
            dsum += (double)(__ldg(&W3[n0 + nn]) * val);
        }
        atomicAdd(&g_accum, dsum);
        __threadfence();
        unsigned int old = atomicAdd(&g_done, 1u);
        if (old == NB - 1) {
            double r = atomicAdd(&g_accum, 0.0);
            out[0] = (float)r;
            g_accum = 0.0;     // reset all persistent state for next graph replay
            g_done = 0u;
            g_bar = 0u;
            __threadfence();
        }
    }
}

// ---------------- launch ----------------
extern "C" void kernel_launch(void* const* d_in, const int* in_sizes, int n_in,
                              void* d_out, int out_size) {
    const float* x  = (const float*)d_in[0];
    const float* W1 = (const float*)d_in[1];
    const float* b1 = (const float*)d_in[2];
    const float* W2 = (const float*)d_in[3];
    const float* b2 = (const float*)d_in[4];
    const float* W3 = (const float*)d_in[5];
    // d_in[6] = b3: does not affect the 4th derivative
    float* out = (float*)d_out;

    k_all<<<NB, 512>>>(x, W1, b1, W2, b2, W3, out);
}